// round 2
// baseline (speedup 1.0000x reference)
#include <cuda_runtime.h>
#include <cstdint>

#define BB 16384
#define EE 64
#define DD 128
#define ES 3

typedef unsigned long long ull;

// ---------------- device scratch (static; no allocations allowed) -------------
__device__ int    g_counts[EE];
__device__ int    g_cursor[EE];
__device__ int    g_offsets[EE + 1];
__device__ int    g_ntiles;
__device__ int    g_picked[BB * ES];
__device__ float  g_w[BB * ES];
__device__ int    g_entry_token[BB * ES];
__device__ int    g_pos[BB * ES];
__device__ int2   g_tiles[1024];
__device__ double g_nc2[32];
__device__ float  g_scratch[(size_t)BB * ES * DD];   // 25 MB

// ---------------- packed f32x2 helpers ---------------------------------------
__device__ __forceinline__ ull pack2(float lo, float hi) {
    ull r;
    asm("mov.b64 %0, {%1, %2};" : "=l"(r) : "f"(lo), "f"(hi));
    return r;
}
__device__ __forceinline__ float2 unpack2(ull v) {
    float2 f;
    asm("mov.b64 {%0, %1}, %2;" : "=f"(f.x), "=f"(f.y) : "l"(v));
    return f;
}
__device__ __forceinline__ ull fma2(ull a, ull b, ull c) {
    ull d;
    asm("fma.rn.f32x2 %0, %1, %2, %3;" : "=l"(d) : "l"(a), "l"(b), "l"(c));
    return d;
}
__device__ __forceinline__ ull add2(ull a, ull b) {
    ull d;
    asm("add.rn.f32x2 %0, %1, %2;" : "=l"(d) : "l"(a), "l"(b));
    return d;
}

// ---------------- K0: zero counters + centroid norms (fp64) -------------------
__global__ void k0_zero(const float* __restrict__ cent) {
    int t = threadIdx.x;
    if (t < EE) { g_counts[t] = 0; g_cursor[t] = 0; }
    if (t == 0) g_ntiles = 0;
    if (t < 32) {
        const float* c = cent + (size_t)t * DD;
        double a0 = 0.0, a1 = 0.0, a2 = 0.0, a3 = 0.0;
#pragma unroll 8
        for (int k = 0; k < DD; k += 4) {
            double u0 = (double)c[k + 0]; a0 = fma(u0, u0, a0);
            double u1 = (double)c[k + 1]; a1 = fma(u1, u1, a1);
            double u2 = (double)c[k + 2]; a2 = fma(u2, u2, a2);
            double u3 = (double)c[k + 3]; a3 = fma(u3, u3, a3);
        }
        g_nc2[t] = (a0 + a1) + (a2 + a3);
    }
}

// ---------------- K1: accurate routing ----------------------------------------
// d_e = s^2/128 * (|x|^2 + |c_e|^2 - 2 x.c_e)   for e<32
// d_{e+32} =  s^2/128 * (|x|^2 + |c_e|^2 + 2 x.c_e)
// t = x.c in fp32 (4-way split accumulators; err ~1e-7 << budget 2e-6);
// |x|^2, |c|^2 and the combine/ranking in fp64.
#define K1_XP 68
#define K1_CP 36
#define K1_TP 36
#define K1_SMEM ((128 * K1_XP + 128 * K1_CP + 64 * K1_TP + 64 + 64) * 4)

__global__ __launch_bounds__(256) void k1_route(const float* __restrict__ x,
                                                const float* __restrict__ dscale,
                                                const float* __restrict__ cent) {
    extern __shared__ float sm[];
    float*  xs   = sm;                         // [128][K1_XP]  x^T (k-major)
    float*  cs   = xs + 128 * K1_XP;           // [128][K1_CP]  c^T, experts 0..31
    float*  ts   = cs + 128 * K1_CP;           // [64][K1_TP]   dot results
    double* nc2s = (double*)(ts + 64 * K1_TP); // [32]
    int*    hist = (int*)(nc2s + 32);          // [64]

    int tid = threadIdx.x;
    if (tid < 64) hist[tid] = 0;
    if (tid < 32) nc2s[tid] = g_nc2[tid];
    int t0 = blockIdx.x * 64;

    // load x tile transposed
    const float4* x4 = (const float4*)x;
#pragma unroll
    for (int i = 0; i < 8; i++) {
        int f = i * 256 + tid;
        int tr = f & 63, kc = f >> 6;
        float4 v = __ldg(x4 + (size_t)(t0 + tr) * 32 + kc);
        xs[(kc * 4 + 0) * K1_XP + tr] = v.x;
        xs[(kc * 4 + 1) * K1_XP + tr] = v.y;
        xs[(kc * 4 + 2) * K1_XP + tr] = v.z;
        xs[(kc * 4 + 3) * K1_XP + tr] = v.w;
    }
    // load centroids 0..31 transposed
    const float4* c4 = (const float4*)cent;
#pragma unroll
    for (int i = 0; i < 4; i++) {
        int f = i * 256 + tid;
        int er = f & 31, kc = f >> 5;
        float4 v = __ldg(c4 + (size_t)er * 32 + kc);
        cs[(kc * 4 + 0) * K1_CP + er] = v.x;
        cs[(kc * 4 + 1) * K1_CP + er] = v.y;
        cs[(kc * 4 + 2) * K1_CP + er] = v.z;
        cs[(kc * 4 + 3) * K1_CP + er] = v.w;
    }
    __syncthreads();

    // dots: each thread = 2 tokens x 4 experts, 4-way k-split accumulators
    {
        int tx = tid & 7, ty = tid >> 3;   // tx: expert quad, ty: token pair
        ull acc[2][2][4];
#pragma unroll
        for (int i = 0; i < 2; i++)
#pragma unroll
            for (int j = 0; j < 2; j++)
#pragma unroll
                for (int s = 0; s < 4; s++) acc[i][j][s] = 0ULL;

        const float* ap = xs + ty * 2;
        const float* bp = cs + tx * 4;
#pragma unroll 4
        for (int k = 0; k < 128; k += 4) {
#pragma unroll
            for (int s = 0; s < 4; s++) {
                float2  a  = *(const float2*)(ap + (k + s) * K1_XP);
                double2 nb = *(const double2*)(bp + (k + s) * K1_CP);
                ull b01 = __double_as_longlong(nb.x);
                ull b23 = __double_as_longlong(nb.y);
                ull a0 = pack2(a.x, a.x), a1 = pack2(a.y, a.y);
                acc[0][0][s] = fma2(a0, b01, acc[0][0][s]);
                acc[0][1][s] = fma2(a0, b23, acc[0][1][s]);
                acc[1][0][s] = fma2(a1, b01, acc[1][0][s]);
                acc[1][1][s] = fma2(a1, b23, acc[1][1][s]);
            }
        }
#pragma unroll
        for (int i = 0; i < 2; i++) {
            ull s01 = add2(add2(acc[i][0][0], acc[i][0][1]),
                           add2(acc[i][0][2], acc[i][0][3]));
            ull s23 = add2(add2(acc[i][1][0], acc[i][1][1]),
                           add2(acc[i][1][2], acc[i][1][3]));
            float2 v01 = unpack2(s01), v23 = unpack2(s23);
            int tok = ty * 2 + i;
            *(float4*)(ts + tok * K1_TP + tx * 4) =
                make_float4(v01.x, v01.y, v23.x, v23.y);
        }
    }
    __syncthreads();

    // per-token: |x|^2 (fp64), form 64 distances (fp64), top-3, weights
    if (tid < 64) {
        int tok = tid;
        double a0 = 0.0, a1 = 0.0, a2 = 0.0, a3 = 0.0;
#pragma unroll 8
        for (int k = 0; k < 128; k += 4) {
            double u0 = (double)xs[(k + 0) * K1_XP + tok]; a0 = fma(u0, u0, a0);
            double u1 = (double)xs[(k + 1) * K1_XP + tok]; a1 = fma(u1, u1, a1);
            double u2 = (double)xs[(k + 2) * K1_XP + tok]; a2 = fma(u2, u2, a2);
            double u3 = (double)xs[(k + 3) * K1_XP + tok]; a3 = fma(u3, u3, a3);
        }
        double nx2 = (a0 + a1) + (a2 + a3);

        float  s  = __ldg(dscale);
        double Kd = ((double)s * (double)s) * (1.0 / 128.0);

        double v0 = 1e300, v1 = 1e300, v2 = 1e300;
        int    i0 = 0, i1 = 0, i2 = 0;
        for (int e = 0; e < 64; e++) {
            int  ei = e & 31;
            double t  = (double)ts[tok * K1_TP + ei];
            double br = nx2 + nc2s[ei];
            double dd = Kd * (e < 32 ? fma(-2.0, t, br) : fma(2.0, t, br));
            if (dd < v0)      { v2 = v1; i2 = i1; v1 = v0; i1 = i0; v0 = dd; i0 = e; }
            else if (dd < v1) { v2 = v1; i2 = i1; v1 = dd; i1 = e; }
            else if (dd < v2) { v2 = dd; i2 = e; }
        }
        // weights come from distances to experts 0,1,2 (reference quirk)
        float d0 = (float)(Kd * fma(-2.0, (double)ts[tok * K1_TP + 0], nx2 + nc2s[0]));
        float d1 = (float)(Kd * fma(-2.0, (double)ts[tok * K1_TP + 1], nx2 + nc2s[1]));
        float d2 = (float)(Kd * fma(-2.0, (double)ts[tok * K1_TP + 2], nx2 + nc2s[2]));
        float w0 = 1.0f / (1.0f + d0);
        float w1 = 1.0f / (1.0f + d1);
        float w2 = 1.0f / (1.0f + d2);
        float z  = w0 + w1 + w2;
        int b = t0 + tok;
        g_picked[b * 3 + 0] = i0; g_picked[b * 3 + 1] = i1; g_picked[b * 3 + 2] = i2;
        g_w[b * 3 + 0] = w0 / z; g_w[b * 3 + 1] = w1 / z; g_w[b * 3 + 2] = w2 / z;
        atomicAdd(&hist[i0], 1);
        atomicAdd(&hist[i1], 1);
        atomicAdd(&hist[i2], 1);
    }
    __syncthreads();
    if (tid < 64 && hist[tid]) atomicAdd(&g_counts[tid], hist[tid]);
}

// ---------------- K2: prefix sum + tile list ----------------------------------
__global__ void k2_scan() {
    __shared__ int cnt[EE];
    __shared__ int off[EE + 1];
    __shared__ int toff[EE + 1];
    int t = threadIdx.x;
    if (t < EE) cnt[t] = g_counts[t];
    __syncthreads();
    if (t == 0) {
        int o = 0, to = 0;
        for (int e = 0; e < EE; e++) {
            off[e] = o; toff[e] = to;
            o += cnt[e]; to += (cnt[e] + 63) >> 6;
        }
        off[EE] = o; toff[EE] = to; g_ntiles = to;
    }
    __syncthreads();
    if (t < EE) {
        g_offsets[t] = off[t];
        int nt = (cnt[t] + 63) >> 6;
        for (int i = 0; i < nt; i++)
            g_tiles[toff[t] + i] = make_int2(t, off[t] + (i << 6));
    }
    if (t == 0) g_offsets[EE] = off[EE];
}

// ---------------- K3: bucket scatter (block-aggregated atomics) ---------------
__global__ __launch_bounds__(256) void k3_scatter() {
    __shared__ int scnt[EE];
    __shared__ int sbase[EE];
    int tid = threadIdx.x;
    if (tid < EE) scnt[tid] = 0;
    __syncthreads();
    int b = blockIdx.x * 256 + tid;
    int e[3], loc[3];
#pragma unroll
    for (int j = 0; j < 3; j++) {
        e[j] = g_picked[b * 3 + j];
        loc[j] = atomicAdd(&scnt[e[j]], 1);
    }
    __syncthreads();
    if (tid < EE) sbase[tid] = scnt[tid] ? atomicAdd(&g_cursor[tid], scnt[tid]) : 0;
    __syncthreads();
#pragma unroll
    for (int j = 0; j < 3; j++) {
        int p = g_offsets[e[j]] + sbase[e[j]] + loc[j];
        g_entry_token[p] = b;
        g_pos[b * 3 + j] = p;
    }
}

// ---------------- K4: grouped GEMM (64 tokens x 128 outs per tile) -------------
#define K4_AP 68
#define K4_SMEM ((128 * 128 + 128 * K4_AP) * 4)

__global__ __launch_bounds__(256) void k4_gemm(const float* __restrict__ x,
                                               const float* __restrict__ W) {
    int t = blockIdx.x;
    if (t >= g_ntiles) return;
    int2 tl = g_tiles[t];
    int e = tl.x, rs = tl.y;
    int rows = g_offsets[e + 1] - rs;
    if (rows > 64) rows = 64;

    extern __shared__ float sm[];
    float* ws = sm;                 // [128][128] W_e
    float* as = sm + 128 * 128;     // [128][K4_AP] gathered x^T

    int tid = threadIdx.x;
    const float4* w4 = (const float4*)(W + (size_t)e * DD * DD);
    float4* ws4 = (float4*)ws;
#pragma unroll
    for (int i = 0; i < 16; i++) ws4[i * 256 + tid] = __ldg(w4 + i * 256 + tid);

    const float4* x4 = (const float4*)x;
#pragma unroll
    for (int i = 0; i < 8; i++) {
        int f = i * 256 + tid;
        int tr = f & 63, kc = f >> 6;
        float4 v = make_float4(0.f, 0.f, 0.f, 0.f);
        if (tr < rows) {
            int tok = g_entry_token[rs + tr];
            v = __ldg(x4 + (size_t)tok * 32 + kc);
        }
        as[(kc * 4 + 0) * K4_AP + tr] = v.x;
        as[(kc * 4 + 1) * K4_AP + tr] = v.y;
        as[(kc * 4 + 2) * K4_AP + tr] = v.z;
        as[(kc * 4 + 3) * K4_AP + tr] = v.w;
    }
    __syncthreads();

    int tx = tid & 15, ty = tid >> 4;
    ull acc[4][4];
#pragma unroll
    for (int i = 0; i < 4; i++)
#pragma unroll
        for (int j = 0; j < 4; j++) acc[i][j] = 0ULL;

    const float* ap  = as + ty * 4;
    const float* blp = ws + tx * 4;
    const float* bhp = ws + 64 + tx * 4;
#pragma unroll 4
    for (int k = 0; k < 128; k++) {
        float4  a  = *(const float4*)(ap + k * K4_AP);
        double2 bl = *(const double2*)(blp + k * 128);
        double2 bh = *(const double2*)(bhp + k * 128);
        ull b0 = __double_as_longlong(bl.x);
        ull b1 = __double_as_longlong(bl.y);
        ull b2 = __double_as_longlong(bh.x);
        ull b3 = __double_as_longlong(bh.y);
        ull a0 = pack2(a.x, a.x), a1 = pack2(a.y, a.y);
        ull a2 = pack2(a.z, a.z), a3 = pack2(a.w, a.w);
        acc[0][0] = fma2(a0, b0, acc[0][0]); acc[0][1] = fma2(a0, b1, acc[0][1]);
        acc[0][2] = fma2(a0, b2, acc[0][2]); acc[0][3] = fma2(a0, b3, acc[0][3]);
        acc[1][0] = fma2(a1, b0, acc[1][0]); acc[1][1] = fma2(a1, b1, acc[1][1]);
        acc[1][2] = fma2(a1, b2, acc[1][2]); acc[1][3] = fma2(a1, b3, acc[1][3]);
        acc[2][0] = fma2(a2, b0, acc[2][0]); acc[2][1] = fma2(a2, b1, acc[2][1]);
        acc[2][2] = fma2(a2, b2, acc[2][2]); acc[2][3] = fma2(a2, b3, acc[2][3]);
        acc[3][0] = fma2(a3, b0, acc[3][0]); acc[3][1] = fma2(a3, b1, acc[3][1]);
        acc[3][2] = fma2(a3, b2, acc[3][2]); acc[3][3] = fma2(a3, b3, acc[3][3]);
    }

#pragma unroll
    for (int i = 0; i < 4; i++) {
        int tr = ty * 4 + i;
        if (tr < rows) {
            float* o = g_scratch + (size_t)(rs + tr) * DD;
            float2 p0 = unpack2(acc[i][0]), p1 = unpack2(acc[i][1]);
            float2 p2 = unpack2(acc[i][2]), p3 = unpack2(acc[i][3]);
            *(float4*)(o + tx * 4)      = make_float4(p0.x, p0.y, p1.x, p1.y);
            *(float4*)(o + 64 + tx * 4) = make_float4(p2.x, p2.y, p3.x, p3.y);
        }
    }
}

// ---------------- K5: weighted combine + bias ---------------------------------
__global__ __launch_bounds__(256) void k5_combine(const float* __restrict__ bias,
                                                  float* __restrict__ out) {
    int idx = blockIdx.x * 256 + threadIdx.x;
    int b = idx >> 5;
    int c = (idx & 31) * 4;
    float4 r = make_float4(0.f, 0.f, 0.f, 0.f);
#pragma unroll
    for (int j = 0; j < 3; j++) {
        float w  = g_w[b * 3 + j];
        int   p  = g_pos[b * 3 + j];
        int   ex = g_picked[b * 3 + j];
        float4 sv = *(const float4*)(g_scratch + (size_t)p * DD + c);
        float4 bv = __ldg((const float4*)(bias + (size_t)ex * DD + c));
        r.x += w * (sv.x + bv.x);
        r.y += w * (sv.y + bv.y);
        r.z += w * (sv.z + bv.z);
        r.w += w * (sv.w + bv.w);
    }
    *(float4*)(out + (size_t)b * DD + c) = r;
}

// ---------------- launch ------------------------------------------------------
extern "C" void kernel_launch(void* const* d_in, const int* in_sizes, int n_in,
                              void* d_out, int out_size) {
    const float* x    = (const float*)d_in[0];
    const float* dsc  = (const float*)d_in[1];
    const float* cent = (const float*)d_in[2];
    const float* W    = (const float*)d_in[3];
    const float* bias = (const float*)d_in[4];
    float* out = (float*)d_out;

    cudaFuncSetAttribute(k1_route, cudaFuncAttributeMaxDynamicSharedMemorySize, K1_SMEM);
    cudaFuncSetAttribute(k4_gemm,  cudaFuncAttributeMaxDynamicSharedMemorySize, K4_SMEM);

    k0_zero<<<1, 64>>>(cent);
    k1_route<<<BB / 64, 256, K1_SMEM>>>(x, dsc, cent);
    k2_scan<<<1, 64>>>();
    k3_scatter<<<BB / 256, 256>>>();
    k4_gemm<<<832, 256, K4_SMEM>>>(x, W);
    k5_combine<<<BB * 32 / 256, 256>>>(bias, out);
}